// round 2
// baseline (speedup 1.0000x reference)
#include <cuda_runtime.h>

#define EPSF 1e-7f
#define NROWS 2097152
#define RPB 256        // rows per block
#define THREADS 256
#define NBLOCKS (NROWS / RPB)   // 8192
#define INV_B 4.76837158203125e-07f   // 1 / 2097152 (exact, 2^-21)

__device__ double g_accum;

// atan(x), full range, ~1e-6 abs error. MUFU.RCP for |x|>1 branch.
__device__ __forceinline__ float fast_atan(float x) {
    float ax = fabsf(x);
    bool big = ax > 1.0f;
    float z = big ? __fdividef(1.0f, ax) : ax;
    float z2 = z * z;
    float p = -0.0117212f;
    p = fmaf(p, z2, 0.05265332f);
    p = fmaf(p, z2, -0.11643287f);
    p = fmaf(p, z2, 0.19354346f);
    p = fmaf(p, z2, -0.33262347f);
    p = fmaf(p, z2, 0.99997726f);
    float r = p * z;
    if (big) r = 1.57079632679489662f - r;
    return copysignf(r, x);
}

__global__ void init_kernel() { g_accum = 0.0; }

__global__ void final_kernel(float* out) { out[0] = (float)g_accum; }

__global__ void __launch_bounds__(THREADS)
loss_kernel(const float* __restrict__ pred, const float* __restrict__ targ) {
    __shared__ float s_pred[RPB * 30];   // 30720 B
    __shared__ float s_targ[RPB * 5];    //  5120 B
    __shared__ float s_wsum[THREADS / 32];

    const int tid = threadIdx.x;
    const long long base_row = (long long)blockIdx.x * RPB;

    // ---- coalesced staging: pred chunk = 7680 floats = 1920 float4 ----
    {
        const float4* gp = (const float4*)(pred + base_row * 30);
        float4* sp = (float4*)s_pred;
#pragma unroll
        for (int i = 0; i < 8; i++) {
            int idx = tid + i * THREADS;
            if (idx < 1920) sp[idx] = gp[idx];
        }
        // targ chunk = 1280 floats = 320 float4
        const float4* gt = (const float4*)(targ + base_row * 5);
        float4* st = (float4*)s_targ;
        st[tid] = gt[tid];
        if (tid < 64) st[tid + THREADS] = gt[tid + THREADS];
    }
    __syncthreads();

    // ---- per-thread row compute ----
    const float* r = s_pred + tid * 30;
    const float* t = s_targ + tid * 5;

    const int   label = (int)t[0];
    const float tx = t[1], ty = t[2], tw = t[3], th = t[4];

    // target-side CIoU terms (shared across the 3 anchors)
    const float b2x1 = fmaf(-0.5f, tw, tx);
    const float b2x2 = fmaf( 0.5f, tw, tx);
    const float b2y1 = fmaf(-0.5f, th, ty);
    const float b2y2 = fmaf( 0.5f, th, ty);
    const float area2 = tw * th;
    const float at2   = fast_atan(__fdividef(tw, th + EPSF));
    const float b2sx  = b2x1 + b2x2;
    const float b2sy  = b2y1 + b2y2;

    float acc = 0.0f;   // l_bbox + l_conf contributions
    float cls = 0.0f;   // sum of picked log-probs

#pragma unroll
    for (int a = 0; a < 3; a++) {
        const float* q = r + a * 10;
        const float q0 = q[0], q1 = q[1], q2 = q[2], q3 = q[3], q4 = q[4];

        // log-softmax over 5 classes, pick label
        float m = fmaxf(fmaxf(fmaxf(q0, q1), fmaxf(q2, q3)), q4);
        float s = __expf(q0 - m) + __expf(q1 - m) + __expf(q2 - m)
                + __expf(q3 - m) + __expf(q4 - m);
        cls += (q[label] - m) - __logf(s);

        // bbox SSE
        const float x1 = q[6], y1 = q[7], w1 = q[8], h1 = q[9];
        float dx = x1 - tx, dy = y1 - ty, dw = w1 - tw, dh = h1 - th;
        acc = fmaf(dx, dx, acc);
        acc = fmaf(dy, dy, acc);
        acc = fmaf(dw, dw, acc);
        acc = fmaf(dh, dh, acc);

        // CIoU (stop_gradient irrelevant for forward value)
        const float b1x1 = fmaf(-0.5f, w1, x1);
        const float b1x2 = fmaf( 0.5f, w1, x1);
        const float b1y1 = fmaf(-0.5f, h1, y1);
        const float b1y2 = fmaf( 0.5f, h1, y1);

        float iw = fmaxf(fminf(b1x2, b2x2) - fmaxf(b1x1, b2x1), 0.0f);
        float ih = fmaxf(fminf(b1y2, b2y2) - fmaxf(b1y1, b2y1), 0.0f);
        float inter = iw * ih;
        float uni = w1 * h1 + area2 - inter + EPSF;
        float iou = __fdividef(inter, uni);

        float cw = fmaxf(b1x2, b2x2) - fminf(b1x1, b2x1);
        float ch = fmaxf(b1y2, b2y2) - fminf(b1y1, b2y1);
        float c2 = fmaf(cw, cw, fmaf(ch, ch, EPSF));

        float ex = b2sx - (b1x1 + b1x2);
        float ey = b2sy - (b1y1 + b1y2);
        float rho2 = fmaf(ex, ex, ey * ey) * 0.25f;

        float da = at2 - fast_atan(__fdividef(w1, h1 + EPSF));
        float v = 0.40528473456935108f * (da * da);      // 4/pi^2
        float alpha = __fdividef(v, v - iou + (1.0f + EPSF));
        float ciou = iou - (__fdividef(rho2, c2) + v * alpha);

        float e = ciou - q[5];
        acc = fmaf(e, e, acc);
    }

    float total = fmaf(cls, -INV_B, acc);

    // ---- reduce: warp shuffle -> smem -> fp64 atomic ----
#pragma unroll
    for (int o = 16; o > 0; o >>= 1)
        total += __shfl_down_sync(0xffffffffu, total, o);
    if ((tid & 31) == 0) s_wsum[tid >> 5] = total;
    __syncthreads();
    if (tid == 0) {
        float bs = 0.0f;
#pragma unroll
        for (int w = 0; w < THREADS / 32; w++) bs += s_wsum[w];
        atomicAdd(&g_accum, (double)bs);
    }
}

extern "C" void kernel_launch(void* const* d_in, const int* in_sizes, int n_in,
                              void* d_out, int out_size) {
    const float* pred = (const float*)d_in[0];   // (B, 30) float32
    const float* targ = (const float*)d_in[1];   // (B, 5)  float32
    float* out = (float*)d_out;                  // scalar float32

    init_kernel<<<1, 1>>>();
    loss_kernel<<<NBLOCKS, THREADS>>>(pred, targ);
    final_kernel<<<1, 1>>>(out);
}